// round 2
// baseline (speedup 1.0000x reference)
#include <cuda_runtime.h>
#include <cuda_bf16.h>

// CharEmb: fused embedding-gather + raw-reshape + Conv1d(K=3, valid) + max-pool.
// Shapes: char_ids [32,512,32] i32, emb_table [101,64] f32,
//         conv_w [128,64,3] f32, conv_b [128] f32 -> out [32,512,128] f32.
//
// Key semantic: reference does .view(-1, E, C) = raw reinterpretation of the
// contiguous [B*S, C, E] gather buffer. So per word, x[e, c] = flat[e*32 + c]
// where flat[i] = emb_table[ids[i>>6], i & 63].
//
// Layout: 1 word per 128-thread block; thread f = filter index.
//   Phase 1: cooperative gather of the 2048-float flat buffer into smem.
//   Phase 2: each thread keeps acc[30] in registers; loop e=0..63, load the
//            32-float x row (vectorized float4 broadcast from smem) and the
//            3 weights w[f,e,0..2] (L2-resident), 90 FMAs per e.
//   Phase 3: max over t, add bias, store.

#define NWORDS 16384   // B*S = 32*512
#define C_LEN  32
#define E_DIM  64
#define F_DIM  128
#define T_OUT  30      // C - K + 1
#define FLAT   2048    // C*E per word

__global__ __launch_bounds__(F_DIM) void charemb_kernel(
    const int*   __restrict__ ids,     // [NWORDS, 32]
    const float* __restrict__ table,   // [101, 64]
    const float* __restrict__ w,       // [128, 64, 3]
    const float* __restrict__ bias,    // [128]
    float*       __restrict__ out)     // [NWORDS, 128]
{
    __shared__ __align__(16) float sx[FLAT];

    const int n = blockIdx.x;
    const int f = threadIdx.x;

    // ---- Phase 1: gather flat[i] = table[ids[i>>6]*64 + (i&63)] ----
    const int* idn = ids + n * C_LEN;
    #pragma unroll
    for (int j = 0; j < FLAT / F_DIM; ++j) {
        int i = f + j * F_DIM;
        int c = i >> 6;        // char position within word
        int e = i & 63;        // embedding dim
        sx[i] = table[idn[c] * E_DIM + e];
    }
    __syncthreads();

    // ---- Phase 2: conv accumulate ----
    float acc[T_OUT];
    #pragma unroll
    for (int t = 0; t < T_OUT; ++t) acc[t] = 0.0f;

    const float* wf = w + f * (E_DIM * 3);
    const float4* sx4 = reinterpret_cast<const float4*>(sx);

    #pragma unroll 4
    for (int e = 0; e < E_DIM; ++e) {
        // 32-float x row for this e, broadcast via LDS.128 (all lanes same addr)
        float xv[C_LEN];
        #pragma unroll
        for (int q = 0; q < C_LEN / 4; ++q) {
            float4 v = sx4[e * (C_LEN / 4) + q];
            xv[q * 4 + 0] = v.x;
            xv[q * 4 + 1] = v.y;
            xv[q * 4 + 2] = v.z;
            xv[q * 4 + 3] = v.w;
        }
        float w0 = wf[e * 3 + 0];
        float w1 = wf[e * 3 + 1];
        float w2 = wf[e * 3 + 2];
        #pragma unroll
        for (int t = 0; t < T_OUT; ++t) {
            acc[t] = fmaf(w0, xv[t],
                     fmaf(w1, xv[t + 1],
                     fmaf(w2, xv[t + 2], acc[t])));
        }
    }

    // ---- Phase 3: max over time + bias ----
    float m = acc[0];
    #pragma unroll
    for (int t = 1; t < T_OUT; ++t) m = fmaxf(m, acc[t]);

    out[n * F_DIM + f] = m + bias[f];
}

extern "C" void kernel_launch(void* const* d_in, const int* in_sizes, int n_in,
                              void* d_out, int out_size) {
    const int*   ids   = (const int*)  d_in[0];  // char_ids  [32,512,32]
    const float* table = (const float*)d_in[1];  // emb_table [101,64]
    const float* w     = (const float*)d_in[2];  // conv_w    [128,64,3]
    const float* bias  = (const float*)d_in[3];  // conv_b    [128]
    float* out = (float*)d_out;

    charemb_kernel<<<NWORDS, F_DIM>>>(ids, table, w, bias, out);
}

// round 3
// speedup vs baseline: 3.3301x; 3.3301x over previous
#include <cuda_runtime.h>
#include <cuda_bf16.h>

// CharEmb: fused embedding-gather + raw-reshape + Conv1d(K=3, valid) + max-pool.
// char_ids [32,512,32] i32, emb_table [101,64] f32, conv_w [128,64,3] f32,
// conv_b [128] f32 -> out [32,512,128] f32.
//
// R2 change: weights are transposed once per launch (tiny pre-kernel) into
// __device__ g_wt[j=e*3+k][f] so the main kernel's weight loads are
// lane-coalesced (1 L1 wavefront/LDG instead of 32). R1 was L1TEX-bound
// (98.5%) purely on the f-strided conv_w reads.

#define NWORDS 16384   // B*S
#define C_LEN  32
#define E_DIM  64
#define F_DIM  128
#define T_OUT  30      // C - K + 1
#define FLAT   2048    // C*E per word
#define WSZ    (F_DIM * E_DIM * 3)   // 24576

__device__ float g_wt[WSZ];   // [192][128]: g_wt[(e*3+k)*128 + f]

__global__ __launch_bounds__(256) void transpose_w_kernel(
    const float* __restrict__ w)   // [128][64][3]
{
    int idx = blockIdx.x * blockDim.x + threadIdx.x;
    if (idx < WSZ) {
        int j = idx >> 7;      // e*3+k, 0..191
        int f = idx & 127;
        // coalesced write (f fastest), scattered read (L2-cached, one-time)
        g_wt[idx] = w[f * 192 + j];
    }
}

__global__ __launch_bounds__(F_DIM) void charemb_kernel(
    const int*   __restrict__ ids,     // [NWORDS, 32]
    const float* __restrict__ table,   // [101, 64]
    const float* __restrict__ bias,    // [128]
    float*       __restrict__ out)     // [NWORDS, 128]
{
    __shared__ __align__(16) float sx[FLAT];

    const int n = blockIdx.x;
    const int f = threadIdx.x;

    // ---- Phase 1: gather flat[i] = table[ids[i>>6]*64 + (i&63)] ----
    const int* idn = ids + n * C_LEN;
    #pragma unroll
    for (int j = 0; j < FLAT / F_DIM; ++j) {
        int i = f + j * F_DIM;
        int c = i >> 6;
        int e = i & 63;
        sx[i] = table[idn[c] * E_DIM + e];
    }
    __syncthreads();

    // ---- Phase 2: conv accumulate ----
    float acc[T_OUT];
    #pragma unroll
    for (int t = 0; t < T_OUT; ++t) acc[t] = 0.0f;

    const float4* sx4 = reinterpret_cast<const float4*>(sx);
    const float*  wtf = g_wt + f;   // lane-coalesced weight base

    #pragma unroll 4
    for (int e = 0; e < E_DIM; ++e) {
        // 32-float x row for this e (uniform broadcast LDS.128)
        float xv[C_LEN];
        #pragma unroll
        for (int q = 0; q < C_LEN / 4; ++q) {
            float4 v = sx4[e * (C_LEN / 4) + q];
            xv[q * 4 + 0] = v.x;
            xv[q * 4 + 1] = v.y;
            xv[q * 4 + 2] = v.z;
            xv[q * 4 + 3] = v.w;
        }
        // coalesced weight loads: 1 wavefront each, L1-resident (96 KB)
        float w0 = __ldg(wtf + (e * 3 + 0) * F_DIM);
        float w1 = __ldg(wtf + (e * 3 + 1) * F_DIM);
        float w2 = __ldg(wtf + (e * 3 + 2) * F_DIM);
        #pragma unroll
        for (int t = 0; t < T_OUT; ++t) {
            acc[t] = fmaf(w0, xv[t],
                     fmaf(w1, xv[t + 1],
                     fmaf(w2, xv[t + 2], acc[t])));
        }
    }

    // ---- Phase 3: max over time + bias ----
    float m = acc[0];
    #pragma unroll
    for (int t = 1; t < T_OUT; ++t) m = fmaxf(m, acc[t]);

    out[n * F_DIM + f] = m + bias[f];
}

extern "C" void kernel_launch(void* const* d_in, const int* in_sizes, int n_in,
                              void* d_out, int out_size) {
    const int*   ids   = (const int*)  d_in[0];  // char_ids
    const float* table = (const float*)d_in[1];  // emb_table
    const float* w     = (const float*)d_in[2];  // conv_w
    const float* bias  = (const float*)d_in[3];  // conv_b
    float* out = (float*)d_out;

    transpose_w_kernel<<<(WSZ + 255) / 256, 256>>>(w);
    charemb_kernel<<<NWORDS, F_DIM>>>(ids, table, bias, out);
}

// round 5
// speedup vs baseline: 3.4667x; 1.0410x over previous
#include <cuda_runtime.h>
#include <cuda_bf16.h>

// CharEmb fused kernel, R4: R3's f32x2 packing with the gather FIXED.
//
// Raw .view(-1,E,C) semantics derived exactly:
//   x[e,c] = flat[32e+c],  flat[i] = table[ids[i>>6]][i&63]
//   =>  x[e,c] = table[ids[e>>1]][(e&1)*32 + c]
// Rows 2j, 2j+1 of x are the two halves of char j's embedding vector.
//
// e-pair packing (acc2[t] = (sum over even e, sum over odd e), fma.rn.f32x2):
//   smem sx2[e2*32+c]       = (table[id[e2]][c], table[id[e2]][c+32])
//   gmem g_wt2[(e2*3+k)][f] = (w[f][2e2][k],     w[f][2e2+1][k])
// Horizontal lo+hi add only in the epilogue.

#define NWORDS 16384
#define C_LEN  32
#define E_DIM  64
#define E2_DIM 32      // e pairs
#define F_DIM  128
#define T_OUT  30
#define W2SZ   (E2_DIM * 3 * F_DIM)   // 12288 float2 = 96 KB

typedef unsigned long long u64;

__device__ u64 g_wt2[W2SZ];   // [(e2*3+k)][f] : packed (w_even, w_odd)

// fma.rn.f32x2: d = a*b + d elementwise on packed fp32 pairs (sm_100+)
#define FMA2(acc, a, b) \
    asm("fma.rn.f32x2 %0, %1, %2, %0;" : "+l"(acc) : "l"(a), "l"(b))

__global__ __launch_bounds__(256) void transpose_w_kernel(
    const float* __restrict__ w)   // [128][64][3]
{
    int idx = blockIdx.x * blockDim.x + threadIdx.x;
    if (idx < W2SZ) {
        int j  = idx >> 7;       // e2*3 + k, 0..95
        int f  = idx & 127;
        int e2 = j / 3;
        int k  = j - e2 * 3;
        float lo = w[f * 192 + (2 * e2)     * 3 + k];
        float hi = w[f * 192 + (2 * e2 + 1) * 3 + k];
        float2 v = make_float2(lo, hi);
        g_wt2[idx] = *reinterpret_cast<u64*>(&v);
    }
}

__global__ __launch_bounds__(F_DIM) void charemb_kernel(
    const int*   __restrict__ ids,     // [NWORDS, 32]
    const float* __restrict__ table,   // [101, 64]
    const float* __restrict__ bias,    // [128]
    float*       __restrict__ out)     // [NWORDS, 128]
{
    // sx2[e2*32 + c] = (x[2e2][c], x[2e2+1][c]), 8 KB
    __shared__ __align__(16) float2 sx2[E2_DIM * C_LEN];

    const int n = blockIdx.x;
    const int f = threadIdx.x;

    // ---- Phase 1: gather (FIXED). x[2e2][c] = table[id[e2]][c],
    //      x[2e2+1][c] = table[id[e2]][c+32]: same row, +32 column offset. ----
    const int* idn = ids + n * C_LEN;
    #pragma unroll
    for (int j = 0; j < (E2_DIM * C_LEN) / F_DIM; ++j) {   // 8 iters
        int p  = f + j * F_DIM;
        int e2 = p >> 5;           // char index
        int c  = p & 31;           // conv position
        const float* row = table + idn[e2] * E_DIM;
        sx2[p] = make_float2(row[c], row[c + 32]);
    }
    __syncthreads();

    // ---- Phase 2: packed conv accumulate ----
    u64 acc2[T_OUT];
    #pragma unroll
    for (int t = 0; t < T_OUT; ++t) acc2[t] = 0ull;

    const u64* wtf = g_wt2 + f;                 // lane-coalesced
    const ulonglong2* row2base = reinterpret_cast<const ulonglong2*>(sx2);

    #pragma unroll 4
    for (int e2 = 0; e2 < E2_DIM; ++e2) {
        u64 w0 = __ldg(wtf + (e2 * 3 + 0) * F_DIM);
        u64 w1 = __ldg(wtf + (e2 * 3 + 1) * F_DIM);
        u64 w2 = __ldg(wtf + (e2 * 3 + 2) * F_DIM);
        const ulonglong2* row2 = row2base + e2 * (C_LEN / 2);

        #pragma unroll
        for (int q = 0; q < C_LEN / 2; ++q) {   // 16 x LDS.128 (broadcast)
            ulonglong2 X = row2[q];
            const int c0 = 2 * q, c1 = 2 * q + 1;
            // position c contributes: acc[c] w/ w0, acc[c-1] w/ w1, acc[c-2] w/ w2
            if (c0 <= T_OUT - 1)            FMA2(acc2[c0],     w0, X.x);
            if (c0 >= 1 && c0 <= T_OUT)     FMA2(acc2[c0 - 1], w1, X.x);
            if (c0 >= 2)                    FMA2(acc2[c0 - 2], w2, X.x);
            if (c1 <= T_OUT - 1)            FMA2(acc2[c1],     w0, X.y);
            if (c1 >= 1 && c1 <= T_OUT)     FMA2(acc2[c1 - 1], w1, X.y);
            if (c1 >= 2)                    FMA2(acc2[c1 - 2], w2, X.y);
        }
    }

    // ---- Phase 3: horizontal add (even-e + odd-e), max, bias ----
    float m = -__FLT_MAX__;
    #pragma unroll
    for (int t = 0; t < T_OUT; ++t) {
        u64 v = acc2[t];
        float lo = __int_as_float((int)(v & 0xffffffffull));
        float hi = __int_as_float((int)(v >> 32));
        m = fmaxf(m, lo + hi);
    }

    out[n * F_DIM + f] = m + bias[f];
}

extern "C" void kernel_launch(void* const* d_in, const int* in_sizes, int n_in,
                              void* d_out, int out_size) {
    const int*   ids   = (const int*)  d_in[0];  // char_ids
    const float* table = (const float*)d_in[1];  // emb_table
    const float* w     = (const float*)d_in[2];  // conv_w
    const float* bias  = (const float*)d_in[3];  // conv_b
    float* out = (float*)d_out;

    transpose_w_kernel<<<(W2SZ + 255) / 256, 256>>>(w);
    charemb_kernel<<<NWORDS, F_DIM>>>(ids, table, bias, out);
}